// round 2
// baseline (speedup 1.0000x reference)
#include <cuda_runtime.h>
#include <math.h>

// Problem constants
#define O_DIM 32
#define I_DIM 32
#define K_DIM 13
#define N_DIM 4096
#define IK    (I_DIM * K_DIM)    // 416
#define WSIZE (O_DIM * IK)       // 13312 floats = 53 KB

#define G_ELEMS (N_DIM * IK)     // 1,703,936 floats = 6.8 MB

// Scratch for the materialized gather (device global: allocation-free)
__device__ float g_scratch[G_ELEMS];

// ---------------------------------------------------------------------------
// Kernel 1: materialize g[n,e] = x[(e/13)*N + shifts[n*13 + (e%13)]]
// e indexes (i,k) in mask-row order: e = i*13 + k.
// ---------------------------------------------------------------------------
#define G_THREADS 256
#define G_BLOCKS  (G_ELEMS / G_THREADS)   // 6656, divides exactly

__global__ void __launch_bounds__(G_THREADS) gather_kernel(
    const float* __restrict__ x,       // (I, N)
    const int*   __restrict__ shifts)  // (N, K)
{
    const int idx = blockIdx.x * G_THREADS + threadIdx.x;
    const int n = idx / IK;
    const int e = idx - n * IK;
    const int i = e / K_DIM;
    const int k = e - i * K_DIM;
    const int s = shifts[n * K_DIM + k];
    g_scratch[idx] = x[i * N_DIM + s];
}

// ---------------------------------------------------------------------------
// Kernel 2: per-warp independent dot products, no per-iteration barriers.
// Warp w of each block owns output row o = w. Block strides over n.
// ---------------------------------------------------------------------------
#define THREADS 1024
#define BLOCKS  304              // 152 SMs * 2 resident blocks

__global__ void __launch_bounds__(THREADS, 2) dot_kernel(
    const float* __restrict__ W,       // (O, I, K)
    const float* __restrict__ b,       // (O,)
    const float* __restrict__ mask,    // (N, O, I, K)
    float*       __restrict__ out)     // (O, N)
{
    __shared__ float Wsh[WSIZE];

    const int tid  = threadIdx.x;
    const int warp = tid >> 5;   // warp == o
    const int lane = tid & 31;

    #pragma unroll
    for (int e = tid; e < WSIZE; e += THREADS)
        Wsh[e] = W[e];
    __syncthreads();             // the ONLY barrier

    // Hoist this warp's W row into registers: 13 values per lane.
    float wreg[K_DIM];
    #pragma unroll
    for (int j = 0; j < K_DIM; ++j)
        wreg[j] = Wsh[warp * IK + j * 32 + lane];

    const float bias = b[warp];
    const float e_const = 2.718281828459045f;
    const float scale = (2.0f + 2.0f * e_const) / (e_const - 1.0f);

    for (int n = blockIdx.x; n < N_DIM; n += gridDim.x) {
        const float* __restrict__ mrow = mask + ((size_t)n * O_DIM + warp) * IK;
        const float* __restrict__ grow = g_scratch + (size_t)n * IK;

        float sum = 0.0f;
        #pragma unroll
        for (int j = 0; j < K_DIM; ++j) {
            const int e = j * 32 + lane;   // 13*32 == 416 exactly
            sum += mrow[e] * wreg[j] * grow[e];
        }

        #pragma unroll
        for (int off = 16; off > 0; off >>= 1)
            sum += __shfl_xor_sync(0xffffffffu, sum, off);

        if (lane == 0) {
            const float y   = sum + bias;
            const float sig = 1.0f / (1.0f + expf(-y));
            out[warp * N_DIM + n] = (sig - 0.5f) * scale;
        }
    }
}

extern "C" void kernel_launch(void* const* d_in, const int* in_sizes, int n_in,
                              void* d_out, int out_size) {
    const float* x      = (const float*)d_in[0];
    const float* Wconv  = (const float*)d_in[1];
    const float* bconv  = (const float*)d_in[2];
    const float* mask   = (const float*)d_in[3];
    const int*   shifts = (const int*)d_in[4];
    float* out          = (float*)d_out;

    gather_kernel<<<G_BLOCKS, G_THREADS>>>(x, shifts);
    dot_kernel<<<BLOCKS, THREADS>>>(Wconv, bconv, mask, out);
}

// round 3
// speedup vs baseline: 1.3196x; 1.3196x over previous
#include <cuda_runtime.h>
#include <math.h>

// Problem constants
#define O_DIM 32
#define I_DIM 32
#define K_DIM 13
#define N_DIM 4096
#define IK    (I_DIM * K_DIM)    // 416
#define WSIZE (O_DIM * IK)       // 13312 floats = 53 KB

#define THREADS 512              // 16 warps; warp w handles o = 2w, 2w+1
#define BLOCKS  304              // 152 SMs * 2 resident blocks

__global__ void __launch_bounds__(THREADS, 2) plaq_kernel(
    const float* __restrict__ x,       // (I, N)
    const float* __restrict__ W,       // (O, I, K)
    const float* __restrict__ b,       // (O,)
    const float* __restrict__ mask,    // (N, O, I, K)
    const int*   __restrict__ shifts,  // (N, K)
    float*       __restrict__ out)     // (O, N)
{
    __shared__ __align__(16) float Wsh[WSIZE];
    __shared__ __align__(16) float gsh[2][IK];

    const int tid  = threadIdx.x;
    const int warp = tid >> 5;
    const int lane = tid & 31;
    const int o0 = warp * 2;
    const int o1 = o0 + 1;

    // Load W once per block
    #pragma unroll
    for (int e = tid; e < WSIZE; e += THREADS)
        Wsh[e] = W[e];

    // Per-thread gather coordinates (threads 0..415 participate)
    const int gi = tid / K_DIM;
    const int gk = tid - gi * K_DIM;

    // Prime the first gather buffer
    int n = blockIdx.x;
    if (tid < IK) {
        const int s = shifts[n * K_DIM + gk];
        gsh[0][tid] = x[gi * N_DIM + s];
    }
    __syncthreads();

    const float bias0 = b[o0];
    const float bias1 = b[o1];
    const float e_const = 2.718281828459045f;
    const float scale = (2.0f + 2.0f * e_const) / (e_const - 1.0f);

    const float4* __restrict__ W4_0 = (const float4*)(Wsh + o0 * IK);
    const float4* __restrict__ W4_1 = (const float4*)(Wsh + o1 * IK);

    int p = 0;
    for (; n < N_DIM; n += BLOCKS) {
        // ---- Prefetch next n's gather into registers (hidden under mask phase)
        const int nn = n + BLOCKS;
        const bool pf = (tid < IK) && (nn < N_DIM);
        float gval = 0.0f;
        if (pf) {
            const int s = shifts[nn * K_DIM + gk];
            gval = x[gi * N_DIM + s];
        }

        // ---- Main dot: 104 float4 per o-row; lane covers c = lane, +32, +64 (+96 for lanes<8)
        const float4* __restrict__ m4_0 =
            (const float4*)(mask + ((size_t)n * O_DIM + o0) * IK);
        const float4* __restrict__ m4_1 =
            (const float4*)(mask + ((size_t)n * O_DIM + o1) * IK);
        const float4* __restrict__ g4 = (const float4*)gsh[p];

        float s0 = 0.0f, s1 = 0.0f;
        #pragma unroll
        for (int j = 0; j < 3; ++j) {
            const int c = j * 32 + lane;
            const float4 g  = g4[c];
            const float4 ma = m4_0[c];
            const float4 wa = W4_0[c];
            const float4 mb = m4_1[c];
            const float4 wb = W4_1[c];
            s0 += ma.x*wa.x*g.x + ma.y*wa.y*g.y + ma.z*wa.z*g.z + ma.w*wa.w*g.w;
            s1 += mb.x*wb.x*g.x + mb.y*wb.y*g.y + mb.z*wb.z*g.z + mb.w*wb.w*g.w;
        }
        if (lane < 8) {   // tail: chunks 96..103
            const int c = 96 + lane;
            const float4 g  = g4[c];
            const float4 ma = m4_0[c];
            const float4 wa = W4_0[c];
            const float4 mb = m4_1[c];
            const float4 wb = W4_1[c];
            s0 += ma.x*wa.x*g.x + ma.y*wa.y*g.y + ma.z*wa.z*g.z + ma.w*wa.w*g.w;
            s1 += mb.x*wb.x*g.x + mb.y*wb.y*g.y + mb.z*wb.z*g.z + mb.w*wb.w*g.w;
        }

        // ---- Warp reductions
        #pragma unroll
        for (int off = 16; off > 0; off >>= 1) {
            s0 += __shfl_xor_sync(0xffffffffu, s0, off);
            s1 += __shfl_xor_sync(0xffffffffu, s1, off);
        }

        if (lane == 0) {
            const float y0 = s0 + bias0;
            const float y1 = s1 + bias1;
            out[o0 * N_DIM + n] = (1.0f / (1.0f + expf(-y0)) - 0.5f) * scale;
            out[o1 * N_DIM + n] = (1.0f / (1.0f + expf(-y1)) - 0.5f) * scale;
        }

        // ---- Commit prefetched gather, flip buffers
        if (pf) gsh[p ^ 1][tid] = gval;
        __syncthreads();
        p ^= 1;
    }
}

extern "C" void kernel_launch(void* const* d_in, const int* in_sizes, int n_in,
                              void* d_out, int out_size) {
    const float* x      = (const float*)d_in[0];
    const float* Wconv  = (const float*)d_in[1];
    const float* bconv  = (const float*)d_in[2];
    const float* mask   = (const float*)d_in[3];
    const int*   shifts = (const int*)d_in[4];
    float* out          = (float*)d_out;

    plaq_kernel<<<BLOCKS, THREADS>>>(x, Wconv, bconv, mask, shifts, out);
}